// round 1
// baseline (speedup 1.0000x reference)
#include <cuda_runtime.h>
#include <math.h>

// Problem constants
#define TT    1024      // tokens = B*S
#define DIM   512       // d_model
#define NG    8         // groups
#define NE    8         // experts per group
#define NPAIR 64        // G*E
#define HDIM  1024      // 2*d

// ---------------- scratch (static device globals; no allocation) ----------------
__device__ int   d_cnt[NPAIR];
__device__ int   d_tok[NPAIR][TT];     // token index per pair slot
__device__ int   d_asg[NPAIR][TT];     // assignment index (t*4 + slot) per pair slot
__device__ float d_w[TT * 4];          // combined weight per assignment
__device__ float d_H[TT * 4][HDIM];    // layer-1 activations per assignment
__device__ float d_Y[TT * 4][DIM];     // layer-2 outputs per assignment

// ---------------- f32x2 packed-FMA helpers (sm_103a) ----------------
__device__ __forceinline__ unsigned long long fma_f32x2(unsigned long long a,
                                                        unsigned long long b,
                                                        unsigned long long c) {
    unsigned long long d;
    asm("fma.rn.f32x2 %0, %1, %2, %3;" : "=l"(d) : "l"(a), "l"(b), "l"(c));
    return d;
}
__device__ __forceinline__ unsigned long long pack2(float lo, float hi) {
    unsigned long long r;
    asm("mov.b64 %0, {%1, %2};" : "=l"(r) : "f"(lo), "f"(hi));
    return r;
}
__device__ __forceinline__ void unpack2(unsigned long long v, float& lo, float& hi) {
    asm("mov.b64 {%0, %1}, %2;" : "=f"(lo), "=f"(hi) : "l"(v));
}

// ---------------- kernel 0: reset pair counters ----------------
__global__ void zero_cnt_kernel() {
    if (threadIdx.x < NPAIR) d_cnt[threadIdx.x] = 0;
}

// ---------------- kernel 1: routing (one warp per token) ----------------
__global__ void route_kernel(const float* __restrict__ x,
                             const float* __restrict__ g1,
                             const float* __restrict__ g2) {
    int t = (blockIdx.x * blockDim.x + threadIdx.x) >> 5;
    int lane = threadIdx.x & 31;
    if (t >= TT) return;
    const float* xt = x + (size_t)t * DIM;

    // ---- level-1 logits: x_t @ g1  (g1 is [d, G]) ----
    float a[NG];
#pragma unroll
    for (int g = 0; g < NG; g++) a[g] = 0.f;
    for (int i = lane; i < DIM; i += 32) {
        float xv = xt[i];
        const float* gp = g1 + (size_t)i * NG;
#pragma unroll
        for (int g = 0; g < NG; g++) a[g] += xv * gp[g];
    }
#pragma unroll
    for (int off = 16; off; off >>= 1)
#pragma unroll
        for (int g = 0; g < NG; g++) a[g] += __shfl_xor_sync(0xffffffffu, a[g], off);

    // top-2 groups (stable: lower index wins ties, like jax top_k)
    int i1 = 0; float v1 = a[0];
#pragma unroll
    for (int g = 1; g < NG; g++) if (a[g] > v1) { v1 = a[g]; i1 = g; }
    int i2 = -1; float v2 = -1e30f;
#pragma unroll
    for (int g = 0; g < NG; g++) if (g != i1 && a[g] > v2) { v2 = a[g]; i2 = g; }
    float e2 = expf(v2 - v1);
    float inv = 1.f / (1.f + e2);
    int   gs[2]  = { i1, i2 };
    float c1w[2] = { inv, e2 * inv };

    // ---- level-2 logits for the two selected groups (g2 is [G, d, E]) ----
    float b[2 * NE];
#pragma unroll
    for (int q = 0; q < 2 * NE; q++) b[q] = 0.f;
    const float* p0base = g2 + (size_t)gs[0] * DIM * NE;
    const float* p1base = g2 + (size_t)gs[1] * DIM * NE;
    for (int i = lane; i < DIM; i += 32) {
        float xv = xt[i];
        const float* p0 = p0base + (size_t)i * NE;
        const float* p1 = p1base + (size_t)i * NE;
#pragma unroll
        for (int e = 0; e < NE; e++) { b[e] += xv * p0[e]; b[NE + e] += xv * p1[e]; }
    }
#pragma unroll
    for (int off = 16; off; off >>= 1)
#pragma unroll
        for (int q = 0; q < 2 * NE; q++) b[q] += __shfl_xor_sync(0xffffffffu, b[q], off);

    if (lane == 0) {
#pragma unroll
        for (int r = 0; r < 2; r++) {
            int j1 = 0; float u1 = b[r * NE + 0];
#pragma unroll
            for (int e = 1; e < NE; e++) if (b[r * NE + e] > u1) { u1 = b[r * NE + e]; j1 = e; }
            int j2 = -1; float u2 = -1e30f;
#pragma unroll
            for (int e = 0; e < NE; e++) if (e != j1 && b[r * NE + e] > u2) { u2 = b[r * NE + e]; j2 = e; }
            float f2   = expf(u2 - u1);
            float inv2 = 1.f / (1.f + f2);
            int   pe[2]  = { j1, j2 };
            float c2w[2] = { inv2, f2 * inv2 };
            int g = gs[r];
#pragma unroll
            for (int rr = 0; rr < 2; rr++) {
                int pair = g * NE + pe[rr];
                int slot = r * 2 + rr;
                int pos  = atomicAdd(&d_cnt[pair], 1);
                d_tok[pair][pos] = t;
                d_asg[pair][pos] = t * 4 + slot;
                d_w[t * 4 + slot] = c1w[r] * c2w[rr];
            }
        }
    }
}

// ---------------- kernels 2/3: per-pair tiled GEMM ----------------
// BM=64 rows (tokens), BN=128 cols, BK=16. 256 threads, each computes 4x8 via f32x2.
// LAYER2=false: X = x gathered by token, Out = d_H, RELU on.
// LAYER2=true : X = d_H gathered by assignment, Out = d_Y.
template <int K, int N, bool RELU, bool LAYER2>
__global__ __launch_bounds__(256) void moe_gemm(const float* __restrict__ Xparam,
                                                const float* __restrict__ Wt,
                                                const float* __restrict__ bias) {
    constexpr int BM = 64, BN = 128, BK = 16;
    int pair = blockIdx.y;
    int n0   = blockIdx.x * BN;
    int count = d_cnt[pair];
    if (count == 0) return;

    const float* Xsrc = LAYER2 ? &d_H[0][0] : Xparam;
    float*       Out  = LAYER2 ? &d_Y[0][0] : &d_H[0][0];
    const int*   rows = LAYER2 ? d_asg[pair] : d_tok[pair];

    const float* Wp = Wt + (size_t)pair * K * N;
    const float* bp = bias + (size_t)pair * N;

    __shared__ float Xs[BM][BK];
    __shared__ float Ws[BK][BN];

    int tid = threadIdx.x;
    int tx = tid & 15;   // n-dir, 16 threads x 8 cols = 128
    int ty = tid >> 4;   // m-dir, 16 threads x 4 rows = 64

    // per-thread X-load coords: one float4 each
    int xm = tid >> 2;          // 0..63
    int xk = (tid & 3) * 4;     // 0,4,8,12

    for (int m0 = 0; m0 < count; m0 += BM) {
        unsigned long long acc[4][4];   // [row][col-pair], each packs 2 fp32
#pragma unroll
        for (int i = 0; i < 4; i++)
#pragma unroll
            for (int j = 0; j < 4; j++) acc[i][j] = 0ull;

        int grow = m0 + xm;
        const float* xrow = (grow < count) ? (Xsrc + (size_t)rows[grow] * K) : (const float*)0;

        for (int k0 = 0; k0 < K; k0 += BK) {
            // load X tile (gathered rows)
            float4 xv = make_float4(0.f, 0.f, 0.f, 0.f);
            if (xrow) xv = *reinterpret_cast<const float4*>(xrow + k0 + xk);
            Xs[xm][xk + 0] = xv.x; Xs[xm][xk + 1] = xv.y;
            Xs[xm][xk + 2] = xv.z; Xs[xm][xk + 3] = xv.w;
            // load W tile: 2 float4 per thread, coalesced over columns
#pragma unroll
            for (int l = 0; l < 2; l++) {
                int flat = tid * 4 + l * 1024;
                int wr = flat >> 7, wc = flat & 127;
                float4 wv = *reinterpret_cast<const float4*>(Wp + (size_t)(k0 + wr) * N + n0 + wc);
                *reinterpret_cast<float4*>(&Ws[wr][wc]) = wv;
            }
            __syncthreads();
#pragma unroll
            for (int kk = 0; kk < BK; kk++) {
                unsigned long long am2[4];
#pragma unroll
                for (int i = 0; i < 4; i++) {
                    float av = Xs[ty * 4 + i][kk];
                    am2[i] = pack2(av, av);
                }
                unsigned long long bn2[4];
#pragma unroll
                for (int j = 0; j < 4; j++)
                    bn2[j] = *reinterpret_cast<const unsigned long long*>(&Ws[kk][tx * 8 + j * 2]);
#pragma unroll
                for (int i = 0; i < 4; i++)
#pragma unroll
                    for (int j = 0; j < 4; j++)
                        acc[i][j] = fma_f32x2(am2[i], bn2[j], acc[i][j]);
            }
            __syncthreads();
        }
        // epilogue: bias (+relu) and scatter to assignment-indexed rows
#pragma unroll
        for (int i = 0; i < 4; i++) {
            int m = m0 + ty * 4 + i;
            if (m < count) {
                int asg = d_asg[pair][m];
                float* orow = Out + (size_t)asg * N + n0 + tx * 8;
                const float* brow = bp + n0 + tx * 8;
#pragma unroll
                for (int j = 0; j < 4; j++) {
                    float lo, hi;
                    unpack2(acc[i][j], lo, hi);
                    float v0 = lo + brow[j * 2 + 0];
                    float v1 = hi + brow[j * 2 + 1];
                    if (RELU) { v0 = fmaxf(v0, 0.f); v1 = fmaxf(v1, 0.f); }
                    orow[j * 2 + 0] = v0;
                    orow[j * 2 + 1] = v1;
                }
            }
        }
    }
}

// ---------------- kernel 4: weighted combine of the 4 assignments ----------------
__global__ void combine_kernel(float* __restrict__ out) {
    int t = blockIdx.x;
    float w0 = d_w[t * 4 + 0], w1 = d_w[t * 4 + 1];
    float w2 = d_w[t * 4 + 2], w3 = d_w[t * 4 + 3];
    for (int i = threadIdx.x; i < DIM; i += blockDim.x) {
        float s = w0 * d_Y[t * 4 + 0][i] + w1 * d_Y[t * 4 + 1][i]
                + w2 * d_Y[t * 4 + 2][i] + w3 * d_Y[t * 4 + 3][i];
        out[(size_t)t * DIM + i] = s;
    }
}

// ---------------- launch ----------------
extern "C" void kernel_launch(void* const* d_in, const int* in_sizes, int n_in,
                              void* d_out, int out_size) {
    const float* x  = (const float*)d_in[0];
    const float* g1 = (const float*)d_in[1];
    const float* g2 = (const float*)d_in[2];
    const float* W1 = (const float*)d_in[3];
    const float* b1 = (const float*)d_in[4];
    const float* W2 = (const float*)d_in[5];
    const float* b2 = (const float*)d_in[6];
    float* out = (float*)d_out;

    zero_cnt_kernel<<<1, 64>>>();
    route_kernel<<<(TT * 32) / 128, 128>>>(x, g1, g2);
    // layer 1: [count,512] @ [512,1024] + b1, relu  -> d_H
    moe_gemm<DIM, HDIM, true,  false><<<dim3(HDIM / 128, NPAIR), 256>>>(x, W1, b1);
    // layer 2: [count,1024] @ [1024,512] + b2       -> d_Y
    moe_gemm<HDIM, DIM, false, true ><<<dim3(DIM / 128, NPAIR), 256>>>(x, W2, b2);
    combine_kernel<<<TT, 128>>>(out);
}

// round 2
// speedup vs baseline: 1.8955x; 1.8955x over previous
#include <cuda_runtime.h>
#include <math.h>

// Problem constants
#define TT    1024      // tokens = B*S
#define DIM   512       // d_model
#define NG    8         // groups
#define NE    8         // experts per group
#define NPAIR 64        // G*E
#define HDIM  1024      // 2*d

// ---------------- scratch (static device globals; no allocation) ----------------
__device__ int   d_cnt[NPAIR];
__device__ int   d_tok[NPAIR][TT];     // token index per pair slot
__device__ int   d_asg[NPAIR][TT];     // assignment index (t*4 + slot) per pair slot
__device__ float d_w[TT * 4];          // combined weight per assignment
__device__ float d_H[TT * 4][HDIM];    // layer-1 activations per assignment
__device__ float d_Y[TT * 4][DIM];     // layer-2 outputs per assignment

// ---------------- f32x2 packed-FMA helpers (sm_103a) ----------------
__device__ __forceinline__ unsigned long long fma_f32x2(unsigned long long a,
                                                        unsigned long long b,
                                                        unsigned long long c) {
    unsigned long long d;
    asm("fma.rn.f32x2 %0, %1, %2, %3;" : "=l"(d) : "l"(a), "l"(b), "l"(c));
    return d;
}
__device__ __forceinline__ unsigned long long pack2(float lo, float hi) {
    unsigned long long r;
    asm("mov.b64 %0, {%1, %2};" : "=l"(r) : "f"(lo), "f"(hi));
    return r;
}
__device__ __forceinline__ void unpack2(unsigned long long v, float& lo, float& hi) {
    asm("mov.b64 {%0, %1}, %2;" : "=f"(lo), "=f"(hi) : "l"(v));
}

// ---------------- kernel 0: reset pair counters ----------------
__global__ void zero_cnt_kernel() {
    if (threadIdx.x < NPAIR) d_cnt[threadIdx.x] = 0;
}

// ---------------- kernel 1: routing (one warp per token) ----------------
__global__ void route_kernel(const float* __restrict__ x,
                             const float* __restrict__ g1,
                             const float* __restrict__ g2) {
    int t = (blockIdx.x * blockDim.x + threadIdx.x) >> 5;
    int lane = threadIdx.x & 31;
    if (t >= TT) return;
    const float* xt = x + (size_t)t * DIM;

    // ---- level-1 logits: x_t @ g1  (g1 is [d, G]) ----
    float a[NG];
#pragma unroll
    for (int g = 0; g < NG; g++) a[g] = 0.f;
    for (int i = lane; i < DIM; i += 32) {
        float xv = xt[i];
        const float* gp = g1 + (size_t)i * NG;
#pragma unroll
        for (int g = 0; g < NG; g++) a[g] += xv * gp[g];
    }
#pragma unroll
    for (int off = 16; off; off >>= 1)
#pragma unroll
        for (int g = 0; g < NG; g++) a[g] += __shfl_xor_sync(0xffffffffu, a[g], off);

    // top-2 groups (stable: lower index wins ties, like jax top_k)
    int i1 = 0; float v1 = a[0];
#pragma unroll
    for (int g = 1; g < NG; g++) if (a[g] > v1) { v1 = a[g]; i1 = g; }
    int i2 = -1; float v2 = -1e30f;
#pragma unroll
    for (int g = 0; g < NG; g++) if (g != i1 && a[g] > v2) { v2 = a[g]; i2 = g; }
    float e2 = expf(v2 - v1);
    float inv = 1.f / (1.f + e2);
    int   gs[2]  = { i1, i2 };
    float c1w[2] = { inv, e2 * inv };

    // ---- level-2 logits for the two selected groups (g2 is [G, d, E]) ----
    float b[2 * NE];
#pragma unroll
    for (int q = 0; q < 2 * NE; q++) b[q] = 0.f;
    const float* p0base = g2 + (size_t)gs[0] * DIM * NE;
    const float* p1base = g2 + (size_t)gs[1] * DIM * NE;
    for (int i = lane; i < DIM; i += 32) {
        float xv = xt[i];
        const float* p0 = p0base + (size_t)i * NE;
        const float* p1 = p1base + (size_t)i * NE;
#pragma unroll
        for (int e = 0; e < NE; e++) { b[e] += xv * p0[e]; b[NE + e] += xv * p1[e]; }
    }
#pragma unroll
    for (int off = 16; off; off >>= 1)
#pragma unroll
        for (int q = 0; q < 2 * NE; q++) b[q] += __shfl_xor_sync(0xffffffffu, b[q], off);

    if (lane == 0) {
#pragma unroll
        for (int r = 0; r < 2; r++) {
            int j1 = 0; float u1 = b[r * NE + 0];
#pragma unroll
            for (int e = 1; e < NE; e++) if (b[r * NE + e] > u1) { u1 = b[r * NE + e]; j1 = e; }
            int j2 = -1; float u2 = -1e30f;
#pragma unroll
            for (int e = 0; e < NE; e++) if (e != j1 && b[r * NE + e] > u2) { u2 = b[r * NE + e]; j2 = e; }
            float f2   = expf(u2 - u1);
            float inv2 = 1.f / (1.f + f2);
            int   pe[2]  = { j1, j2 };
            float c2w[2] = { inv2, f2 * inv2 };
            int g = gs[r];
#pragma unroll
            for (int rr = 0; rr < 2; rr++) {
                int pair = g * NE + pe[rr];
                int slot = r * 2 + rr;
                int pos  = atomicAdd(&d_cnt[pair], 1);
                d_tok[pair][pos] = t;
                d_asg[pair][pos] = t * 4 + slot;
                d_w[t * 4 + slot] = c1w[r] * c2w[rr];
            }
        }
    }
}

// ---------------- kernels 2/3: per-pair tiled GEMM ----------------
// BM=64 rows, BN=64 cols, BK=16. 128 threads, each computes 8x4 via f32x2.
// Inner loop per k-step: 3x LDS.128 + 16 FFMA2.
// LAYER2=false: X = x gathered by token,      Out = d_H, RELU on.
// LAYER2=true : X = d_H gathered by assignment, Out = d_Y.
template <int K, int N, bool RELU, bool LAYER2>
__global__ __launch_bounds__(128) void moe_gemm(const float* __restrict__ Xparam,
                                                const float* __restrict__ Wt,
                                                const float* __restrict__ bias) {
    constexpr int BM = 64, BN = 64, BK = 16;
    int pair  = blockIdx.y;
    int count = d_cnt[pair];
    if (count == 0) return;
    int n0 = blockIdx.x * BN;

    const float* Xsrc = LAYER2 ? &d_H[0][0] : Xparam;
    float*       Out  = LAYER2 ? &d_Y[0][0] : &d_H[0][0];
    const int*   rows = LAYER2 ? d_asg[pair] : d_tok[pair];

    const float* Wp = Wt + (size_t)pair * K * N + n0;
    const float* bp = bias + (size_t)pair * N + n0;

    __shared__ __align__(16) float Xs[BK][BM + 4];   // transposed: [k][m]
    __shared__ __align__(16) float Ws[BK][BN];

    int tid = threadIdx.x;
    int tx  = tid & 15;    // col group: 4 cols each -> 64
    int ty  = tid >> 4;    // row group: 8 rows each -> 64

    // W-load coords: 2 float4 chunks per thread
    int wr0 = tid >> 4;            // 0..7
    int wr1 = wr0 + 8;             // 8..15
    int wc  = (tid & 15) * 4;

    // X-load coords: 2 float4 chunks per thread (m, 4 consecutive k)
    int xm_a = tid >> 2;           // 0..31
    int xm_b = xm_a + 32;          // 32..63
    int xkc  = (tid & 3) * 4;      // 0,4,8,12

    float4 bias_v = *reinterpret_cast<const float4*>(bp + tx * 4);

    for (int m0 = 0; m0 < count; m0 += BM) {
        int ma = m0 + xm_a, mb = m0 + xm_b;
        const float* rowa = (ma < count) ? (Xsrc + (size_t)rows[ma] * K) : (const float*)0;
        const float* rowb = (mb < count) ? (Xsrc + (size_t)rows[mb] * K) : (const float*)0;

        unsigned long long acc[8][2];
#pragma unroll
        for (int i = 0; i < 8; i++) { acc[i][0] = 0ull; acc[i][1] = 0ull; }

        // prefetch k0 = 0 tile into registers
        float4 xa = make_float4(0.f, 0.f, 0.f, 0.f), xb = xa;
        if (rowa) xa = *reinterpret_cast<const float4*>(rowa + xkc);
        if (rowb) xb = *reinterpret_cast<const float4*>(rowb + xkc);
        float4 wv0 = *reinterpret_cast<const float4*>(Wp + (size_t)wr0 * N + wc);
        float4 wv1 = *reinterpret_cast<const float4*>(Wp + (size_t)wr1 * N + wc);

        for (int k0 = 0; k0 < K; k0 += BK) {
            // commit prefetched tile to smem
            Xs[xkc + 0][xm_a] = xa.x; Xs[xkc + 1][xm_a] = xa.y;
            Xs[xkc + 2][xm_a] = xa.z; Xs[xkc + 3][xm_a] = xa.w;
            Xs[xkc + 0][xm_b] = xb.x; Xs[xkc + 1][xm_b] = xb.y;
            Xs[xkc + 2][xm_b] = xb.z; Xs[xkc + 3][xm_b] = xb.w;
            *reinterpret_cast<float4*>(&Ws[wr0][wc]) = wv0;
            *reinterpret_cast<float4*>(&Ws[wr1][wc]) = wv1;
            __syncthreads();

            // prefetch next tile
            if (k0 + BK < K) {
                int kn = k0 + BK;
                xa = make_float4(0.f, 0.f, 0.f, 0.f); xb = xa;
                if (rowa) xa = *reinterpret_cast<const float4*>(rowa + kn + xkc);
                if (rowb) xb = *reinterpret_cast<const float4*>(rowb + kn + xkc);
                wv0 = *reinterpret_cast<const float4*>(Wp + (size_t)(kn + wr0) * N + wc);
                wv1 = *reinterpret_cast<const float4*>(Wp + (size_t)(kn + wr1) * N + wc);
            }

            // compute
#pragma unroll
            for (int kk = 0; kk < BK; kk++) {
                float4 alo = *reinterpret_cast<const float4*>(&Xs[kk][ty * 8]);
                float4 ahi = *reinterpret_cast<const float4*>(&Xs[kk][ty * 8 + 4]);
                float4 bv  = *reinterpret_cast<const float4*>(&Ws[kk][tx * 4]);
                unsigned long long b01 = pack2(bv.x, bv.y);
                unsigned long long b23 = pack2(bv.z, bv.w);
                float av[8] = { alo.x, alo.y, alo.z, alo.w, ahi.x, ahi.y, ahi.z, ahi.w };
#pragma unroll
                for (int i = 0; i < 8; i++) {
                    unsigned long long aa = pack2(av[i], av[i]);
                    acc[i][0] = fma_f32x2(aa, b01, acc[i][0]);
                    acc[i][1] = fma_f32x2(aa, b23, acc[i][1]);
                }
            }
            __syncthreads();
        }

        // epilogue: bias (+relu), scatter to assignment-indexed rows
#pragma unroll
        for (int i = 0; i < 8; i++) {
            int m = m0 + ty * 8 + i;
            if (m < count) {
                int asg = d_asg[pair][m];
                float v0, v1, v2, v3;
                unpack2(acc[i][0], v0, v1);
                unpack2(acc[i][1], v2, v3);
                v0 += bias_v.x; v1 += bias_v.y; v2 += bias_v.z; v3 += bias_v.w;
                if (RELU) {
                    v0 = fmaxf(v0, 0.f); v1 = fmaxf(v1, 0.f);
                    v2 = fmaxf(v2, 0.f); v3 = fmaxf(v3, 0.f);
                }
                float4 o = make_float4(v0, v1, v2, v3);
                *reinterpret_cast<float4*>(Out + (size_t)asg * N + n0 + tx * 4) = o;
            }
        }
    }
}

// ---------------- kernel 4: weighted combine of the 4 assignments ----------------
__global__ void combine_kernel(float* __restrict__ out) {
    int t = blockIdx.x;
    float w0 = d_w[t * 4 + 0], w1 = d_w[t * 4 + 1];
    float w2 = d_w[t * 4 + 2], w3 = d_w[t * 4 + 3];
    for (int i = threadIdx.x; i < DIM; i += blockDim.x) {
        float s = w0 * d_Y[t * 4 + 0][i] + w1 * d_Y[t * 4 + 1][i]
                + w2 * d_Y[t * 4 + 2][i] + w3 * d_Y[t * 4 + 3][i];
        out[(size_t)t * DIM + i] = s;
    }
}

// ---------------- launch ----------------
extern "C" void kernel_launch(void* const* d_in, const int* in_sizes, int n_in,
                              void* d_out, int out_size) {
    const float* x  = (const float*)d_in[0];
    const float* g1 = (const float*)d_in[1];
    const float* g2 = (const float*)d_in[2];
    const float* W1 = (const float*)d_in[3];
    const float* b1 = (const float*)d_in[4];
    const float* W2 = (const float*)d_in[5];
    const float* b2 = (const float*)d_in[6];
    float* out = (float*)d_out;

    zero_cnt_kernel<<<1, 64>>>();
    route_kernel<<<(TT * 32) / 128, 128>>>(x, g1, g2);
    // layer 1: [count,512] @ [512,1024] + b1, relu  -> d_H
    moe_gemm<DIM, HDIM, true,  false><<<dim3(HDIM / 64, NPAIR), 128>>>(x, W1, b1);
    // layer 2: [count,1024] @ [1024,512] + b2       -> d_Y
    moe_gemm<HDIM, DIM, false, true ><<<dim3(DIM / 64, NPAIR), 128>>>(x, W2, b2);
    combine_kernel<<<TT, 128>>>(out);
}

// round 3
// speedup vs baseline: 1.9002x; 1.0025x over previous
#include <cuda_runtime.h>
#include <math.h>

// Problem constants
#define TT    1024      // tokens = B*S
#define DIM   512       // d_model
#define NG    8         // groups
#define NE    8         // experts per group
#define NPAIR 64        // G*E
#define HDIM  1024      // 2*d

// ---------------- scratch (static device globals; no allocation) ----------------
__device__ int   d_cnt[NPAIR];
__device__ int   d_tok[NPAIR][TT];     // token index per pair slot
__device__ int   d_asg[NPAIR][TT];     // assignment index (t*4 + slot) per pair slot
__device__ float d_w[TT * 4];          // combined weight per assignment
__device__ float d_H[TT * 4][HDIM];    // layer-1 activations per assignment
__device__ float d_Y[TT * 4][DIM];     // layer-2 outputs per assignment

// ---------------- f32x2 packed-FMA helpers (sm_103a) ----------------
__device__ __forceinline__ unsigned long long fma_f32x2(unsigned long long a,
                                                        unsigned long long b,
                                                        unsigned long long c) {
    unsigned long long d;
    asm("fma.rn.f32x2 %0, %1, %2, %3;" : "=l"(d) : "l"(a), "l"(b), "l"(c));
    return d;
}
__device__ __forceinline__ unsigned long long pack2(float lo, float hi) {
    unsigned long long r;
    asm("mov.b64 %0, {%1, %2};" : "=l"(r) : "f"(lo), "f"(hi));
    return r;
}
__device__ __forceinline__ void unpack2(unsigned long long v, float& lo, float& hi) {
    asm("mov.b64 {%0, %1}, %2;" : "=f"(lo), "=f"(hi) : "l"(v));
}

// ---------------- kernel 0: reset pair counters ----------------
__global__ void zero_cnt_kernel() {
    if (threadIdx.x < NPAIR) d_cnt[threadIdx.x] = 0;
}

// ---------------- kernel 1: routing (one warp per token) ----------------
__global__ void route_kernel(const float* __restrict__ x,
                             const float* __restrict__ g1,
                             const float* __restrict__ g2) {
    int t = (blockIdx.x * blockDim.x + threadIdx.x) >> 5;
    int lane = threadIdx.x & 31;
    if (t >= TT) return;
    const float* xt = x + (size_t)t * DIM;

    // ---- level-1 logits: x_t @ g1  (g1 is [d, G]) ----
    float a[NG];
#pragma unroll
    for (int g = 0; g < NG; g++) a[g] = 0.f;
    for (int i = lane; i < DIM; i += 32) {
        float xv = xt[i];
        const float* gp = g1 + (size_t)i * NG;
#pragma unroll
        for (int g = 0; g < NG; g++) a[g] += xv * gp[g];
    }
#pragma unroll
    for (int off = 16; off; off >>= 1)
#pragma unroll
        for (int g = 0; g < NG; g++) a[g] += __shfl_xor_sync(0xffffffffu, a[g], off);

    // top-2 groups (stable: lower index wins ties, like jax top_k)
    int i1 = 0; float v1 = a[0];
#pragma unroll
    for (int g = 1; g < NG; g++) if (a[g] > v1) { v1 = a[g]; i1 = g; }
    int i2 = -1; float v2 = -1e30f;
#pragma unroll
    for (int g = 0; g < NG; g++) if (g != i1 && a[g] > v2) { v2 = a[g]; i2 = g; }
    float e2 = expf(v2 - v1);
    float inv = 1.f / (1.f + e2);
    int   gs[2]  = { i1, i2 };
    float c1w[2] = { inv, e2 * inv };

    // ---- level-2 logits for the two selected groups (g2 is [G, d, E]) ----
    float b[2 * NE];
#pragma unroll
    for (int q = 0; q < 2 * NE; q++) b[q] = 0.f;
    const float* p0base = g2 + (size_t)gs[0] * DIM * NE;
    const float* p1base = g2 + (size_t)gs[1] * DIM * NE;
    for (int i = lane; i < DIM; i += 32) {
        float xv = xt[i];
        const float* p0 = p0base + (size_t)i * NE;
        const float* p1 = p1base + (size_t)i * NE;
#pragma unroll
        for (int e = 0; e < NE; e++) { b[e] += xv * p0[e]; b[NE + e] += xv * p1[e]; }
    }
#pragma unroll
    for (int off = 16; off; off >>= 1)
#pragma unroll
        for (int q = 0; q < 2 * NE; q++) b[q] += __shfl_xor_sync(0xffffffffu, b[q], off);

    if (lane == 0) {
#pragma unroll
        for (int r = 0; r < 2; r++) {
            int j1 = 0; float u1 = b[r * NE + 0];
#pragma unroll
            for (int e = 1; e < NE; e++) if (b[r * NE + e] > u1) { u1 = b[r * NE + e]; j1 = e; }
            int j2 = -1; float u2 = -1e30f;
#pragma unroll
            for (int e = 0; e < NE; e++) if (e != j1 && b[r * NE + e] > u2) { u2 = b[r * NE + e]; j2 = e; }
            float f2   = expf(u2 - u1);
            float inv2 = 1.f / (1.f + f2);
            int   pe[2]  = { j1, j2 };
            float c2w[2] = { inv2, f2 * inv2 };
            int g = gs[r];
#pragma unroll
            for (int rr = 0; rr < 2; rr++) {
                int pair = g * NE + pe[rr];
                int slot = r * 2 + rr;
                int pos  = atomicAdd(&d_cnt[pair], 1);
                d_tok[pair][pos] = t;
                d_asg[pair][pos] = t * 4 + slot;
                d_w[t * 4 + slot] = c1w[r] * c2w[rr];
            }
        }
    }
}

// ---------------- kernels 2/3: per-pair tiled GEMM ----------------
// BM=64 rows, BN=64 cols, BK=16. 128 threads, each computes 8x4 via f32x2.
// Inner loop per k-step: 3x LDS.128 + 16 FFMA2.
// LAYER2=false: X = x gathered by token,      Out = d_H, RELU on.
// LAYER2=true : X = d_H gathered by assignment, Out = d_Y.
template <int K, int N, bool RELU, bool LAYER2>
__global__ __launch_bounds__(128) void moe_gemm(const float* __restrict__ Xparam,
                                                const float* __restrict__ Wt,
                                                const float* __restrict__ bias) {
    constexpr int BM = 64, BN = 64, BK = 16;
    int pair  = blockIdx.y;
    int count = d_cnt[pair];
    if (count == 0) return;
    int n0 = blockIdx.x * BN;

    const float* Xsrc = LAYER2 ? &d_H[0][0] : Xparam;
    float*       Out  = LAYER2 ? &d_Y[0][0] : &d_H[0][0];
    const int*   rows = LAYER2 ? d_asg[pair] : d_tok[pair];

    const float* Wp = Wt + (size_t)pair * K * N + n0;
    const float* bp = bias + (size_t)pair * N + n0;

    __shared__ __align__(16) float Xs[BK][BM + 4];   // transposed: [k][m]
    __shared__ __align__(16) float Ws[BK][BN];

    int tid = threadIdx.x;
    int tx  = tid & 15;    // col group: 4 cols each -> 64
    int ty  = tid >> 4;    // row group: 8 rows each -> 64

    // W-load coords: 2 float4 chunks per thread
    int wr0 = tid >> 4;            // 0..7
    int wr1 = wr0 + 8;             // 8..15
    int wc  = (tid & 15) * 4;

    // X-load coords: 2 float4 chunks per thread (m, 4 consecutive k)
    int xm_a = tid >> 2;           // 0..31
    int xm_b = xm_a + 32;          // 32..63
    int xkc  = (tid & 3) * 4;      // 0,4,8,12

    float4 bias_v = *reinterpret_cast<const float4*>(bp + tx * 4);

    for (int m0 = 0; m0 < count; m0 += BM) {
        int ma = m0 + xm_a, mb = m0 + xm_b;
        const float* rowa = (ma < count) ? (Xsrc + (size_t)rows[ma] * K) : (const float*)0;
        const float* rowb = (mb < count) ? (Xsrc + (size_t)rows[mb] * K) : (const float*)0;

        unsigned long long acc[8][2];
#pragma unroll
        for (int i = 0; i < 8; i++) { acc[i][0] = 0ull; acc[i][1] = 0ull; }

        // prefetch k0 = 0 tile into registers
        float4 xa = make_float4(0.f, 0.f, 0.f, 0.f), xb = xa;
        if (rowa) xa = *reinterpret_cast<const float4*>(rowa + xkc);
        if (rowb) xb = *reinterpret_cast<const float4*>(rowb + xkc);
        float4 wv0 = *reinterpret_cast<const float4*>(Wp + (size_t)wr0 * N + wc);
        float4 wv1 = *reinterpret_cast<const float4*>(Wp + (size_t)wr1 * N + wc);

        for (int k0 = 0; k0 < K; k0 += BK) {
            // commit prefetched tile to smem
            Xs[xkc + 0][xm_a] = xa.x; Xs[xkc + 1][xm_a] = xa.y;
            Xs[xkc + 2][xm_a] = xa.z; Xs[xkc + 3][xm_a] = xa.w;
            Xs[xkc + 0][xm_b] = xb.x; Xs[xkc + 1][xm_b] = xb.y;
            Xs[xkc + 2][xm_b] = xb.z; Xs[xkc + 3][xm_b] = xb.w;
            *reinterpret_cast<float4*>(&Ws[wr0][wc]) = wv0;
            *reinterpret_cast<float4*>(&Ws[wr1][wc]) = wv1;
            __syncthreads();

            // prefetch next tile
            if (k0 + BK < K) {
                int kn = k0 + BK;
                xa = make_float4(0.f, 0.f, 0.f, 0.f); xb = xa;
                if (rowa) xa = *reinterpret_cast<const float4*>(rowa + kn + xkc);
                if (rowb) xb = *reinterpret_cast<const float4*>(rowb + kn + xkc);
                wv0 = *reinterpret_cast<const float4*>(Wp + (size_t)(kn + wr0) * N + wc);
                wv1 = *reinterpret_cast<const float4*>(Wp + (size_t)(kn + wr1) * N + wc);
            }

            // compute
#pragma unroll
            for (int kk = 0; kk < BK; kk++) {
                float4 alo = *reinterpret_cast<const float4*>(&Xs[kk][ty * 8]);
                float4 ahi = *reinterpret_cast<const float4*>(&Xs[kk][ty * 8 + 4]);
                float4 bv  = *reinterpret_cast<const float4*>(&Ws[kk][tx * 4]);
                unsigned long long b01 = pack2(bv.x, bv.y);
                unsigned long long b23 = pack2(bv.z, bv.w);
                float av[8] = { alo.x, alo.y, alo.z, alo.w, ahi.x, ahi.y, ahi.z, ahi.w };
#pragma unroll
                for (int i = 0; i < 8; i++) {
                    unsigned long long aa = pack2(av[i], av[i]);
                    acc[i][0] = fma_f32x2(aa, b01, acc[i][0]);
                    acc[i][1] = fma_f32x2(aa, b23, acc[i][1]);
                }
            }
            __syncthreads();
        }

        // epilogue: bias (+relu), scatter to assignment-indexed rows
#pragma unroll
        for (int i = 0; i < 8; i++) {
            int m = m0 + ty * 8 + i;
            if (m < count) {
                int asg = d_asg[pair][m];
                float v0, v1, v2, v3;
                unpack2(acc[i][0], v0, v1);
                unpack2(acc[i][1], v2, v3);
                v0 += bias_v.x; v1 += bias_v.y; v2 += bias_v.z; v3 += bias_v.w;
                if (RELU) {
                    v0 = fmaxf(v0, 0.f); v1 = fmaxf(v1, 0.f);
                    v2 = fmaxf(v2, 0.f); v3 = fmaxf(v3, 0.f);
                }
                float4 o = make_float4(v0, v1, v2, v3);
                *reinterpret_cast<float4*>(Out + (size_t)asg * N + n0 + tx * 4) = o;
            }
        }
    }
}

// ---------------- kernel 4: weighted combine of the 4 assignments ----------------
__global__ void combine_kernel(float* __restrict__ out) {
    int t = blockIdx.x;
    float w0 = d_w[t * 4 + 0], w1 = d_w[t * 4 + 1];
    float w2 = d_w[t * 4 + 2], w3 = d_w[t * 4 + 3];
    for (int i = threadIdx.x; i < DIM; i += blockDim.x) {
        float s = w0 * d_Y[t * 4 + 0][i] + w1 * d_Y[t * 4 + 1][i]
                + w2 * d_Y[t * 4 + 2][i] + w3 * d_Y[t * 4 + 3][i];
        out[(size_t)t * DIM + i] = s;
    }
}

// ---------------- launch ----------------
extern "C" void kernel_launch(void* const* d_in, const int* in_sizes, int n_in,
                              void* d_out, int out_size) {
    const float* x  = (const float*)d_in[0];
    const float* g1 = (const float*)d_in[1];
    const float* g2 = (const float*)d_in[2];
    const float* W1 = (const float*)d_in[3];
    const float* b1 = (const float*)d_in[4];
    const float* W2 = (const float*)d_in[5];
    const float* b2 = (const float*)d_in[6];
    float* out = (float*)d_out;

    zero_cnt_kernel<<<1, 64>>>();
    route_kernel<<<(TT * 32) / 128, 128>>>(x, g1, g2);
    // layer 1: [count,512] @ [512,1024] + b1, relu  -> d_H
    moe_gemm<DIM, HDIM, true,  false><<<dim3(HDIM / 64, NPAIR), 128>>>(x, W1, b1);
    // layer 2: [count,1024] @ [1024,512] + b2       -> d_Y
    moe_gemm<HDIM, DIM, false, true ><<<dim3(DIM / 64, NPAIR), 128>>>(x, W2, b2);
    combine_kernel<<<TT, 128>>>(out);
}